// round 15
// baseline (speedup 1.0000x reference)
#include <cuda_runtime.h>
#include <stdint.h>

// EarthMoversDistanceRegularizer v13: persistent fused onesweep segmented LSD
// radix sort, smem-atomic-free inner loops:
//   - NO inline next-pass histogram: every pass derives its segment histogram
//     from its own lookback (last tile of a segment writes tot+excl to
//     g_hist and releases histdone[pass][s]; peers wait, then scan)
//   - rank leader uses LDS+STS (not ATOMS-return): ~15x less LSU throughput
//     on uniform-digit passes where most lanes are match-group leaders
//   - uniform tile body for all 4 passes; pass 3 fused with |diff| reduction

#define NSEG     200
#define NMAX     8388608
#define NT       512
#define NWARP    16
#define IT       8
#define TILE     (NT * IT)              // 4096
#define MAXT     2304                   // >= NMAX/TILE + NSEG = 2248
#define GRIDSORT 444                    // 148 SMs x 3 CTAs
#define FULLMASK 0xffffffffu
#define AGGBIT   (1u << 30)
#define INCBIT   (1u << 31)
#define CNTMASK  0x3fffffffu

__device__ uint32_t g_keyA[NMAX];
__device__ uint32_t g_keyB[NMAX];
__device__ int      g_off[NSEG + 1];
__device__ int      g_toff[NSEG + 1];
__device__ int      g_tseg[MAXT];
__device__ uint32_t g_hist[4][NSEG][256];
__device__ uint32_t g_status[4][MAXT][256];
__device__ uint32_t g_histdone[4][NSEG];
__device__ uint32_t g_segdone[3][NSEG];
__device__ uint32_t g_ticket;
__device__ float    g_part[MAXT];

__device__ __forceinline__ uint32_t flipf(uint32_t u) {
    return (u & 0x80000000u) ? ~u : (u | 0x80000000u);
}
__device__ __forceinline__ float unflip(uint32_t k) {
    uint32_t u = (k & 0x80000000u) ? (k & 0x7fffffffu) : ~k;
    return __uint_as_float(u);
}
__device__ __forceinline__ void st_rlx(uint32_t* p, uint32_t v) {
    asm volatile("st.relaxed.gpu.u32 [%0], %1;" :: "l"(p), "r"(v) : "memory");
}
__device__ __forceinline__ uint32_t ld_rlx(const uint32_t* p) {
    uint32_t v;
    asm volatile("ld.relaxed.gpu.u32 %0, [%1];" : "=r"(v) : "l"(p) : "memory");
    return v;
}
__device__ __forceinline__ uint32_t ld_acq(const uint32_t* p) {
    uint32_t v;
    asm volatile("ld.acquire.gpu.u32 %0, [%1];" : "=r"(v) : "l"(p) : "memory");
    return v;
}
// Release add (no return); preceded by __syncthreads it publishes the whole
// block's prior writes to a paired acquire reader.
__device__ __forceinline__ void red_release(uint32_t* p, uint32_t v) {
    asm volatile("red.release.gpu.global.add.u32 [%0], %1;" :: "l"(p), "r"(v)
                 : "memory");
}

struct SortSmem {
    uint32_t cnt[256][17];   // padded: conflict-free leader LDS/STS + scan
    uint32_t exch[TILE];
    uint32_t loc[256];
    uint32_t fix[256];
    uint32_t wsum[8];
    float    red[NWARP];
    int      tk;
};

// ---------------------------------------------------------------------------
// Exclusive prefix over values held by threads 0..255 (others pass 0).
__device__ __forceinline__ uint32_t scan256(uint32_t v, int tid, uint32_t* s_wsum) {
    int lane = tid & 31, w = tid >> 5;
    uint32_t inc = v;
#pragma unroll
    for (int o = 1; o < 32; o <<= 1) {
        uint32_t t = __shfl_up_sync(FULLMASK, inc, o);
        if (lane >= o) inc += t;
    }
    if (lane == 31 && w < 8) s_wsum[w] = inc;
    __syncthreads();
    if (w == 0 && lane < 8) {
        uint32_t x0 = s_wsum[lane];
        uint32_t i2 = x0;
#pragma unroll
        for (int o = 1; o < 8; o <<= 1) {
            uint32_t t = __shfl_up_sync(0xffu, i2, o);
            if (lane >= o) i2 += t;
        }
        s_wsum[lane] = i2 - x0;
    }
    __syncthreads();
    return inc - v + ((tid < 256) ? s_wsum[w] : 0u);
}

// ---------------------------------------------------------------------------
__global__ void k_setup(const int* __restrict__ seg, int n) {
    __shared__ uint32_t s_wsum[8];
    int tid = threadIdx.x;
    if (tid <= NSEG) {
        int lo = 0, hi = n;
        while (lo < hi) {
            int mid = (lo + hi) >> 1;
            if (seg[mid] < tid) lo = mid + 1; else hi = mid;
        }
        g_off[tid] = lo;
    }
    __syncthreads();
    uint32_t nt = 0;
    if (tid < NSEG) {
        int len = g_off[tid + 1] - g_off[tid];
        nt = (uint32_t)((len + TILE - 1) / TILE);
    }
    uint32_t excl = scan256(nt, tid, s_wsum);
    if (tid <= NSEG) g_toff[tid] = (int)excl;
    for (int t = tid; t < MAXT; t += 256) g_tseg[t] = -1;
    __syncthreads();
    if (tid < NSEG)
        for (uint32_t t = 0; t < nt; t++) g_tseg[excl + t] = tid;
}

// ---------------------------------------------------------------------------
__global__ void k_zero() {
    const int gtid = blockIdx.x * blockDim.x + threadIdx.x;
    const int gstr = gridDim.x * blockDim.x;
    uint32_t* p = &g_status[0][0][0];
    for (int i = gtid; i < 4 * MAXT * 256; i += gstr) p[i] = 0;
    uint32_t* hd = &g_histdone[0][0];
    for (int i = gtid; i < 4 * NSEG; i += gstr) hd[i] = 0;
    uint32_t* d = &g_segdone[0][0];
    for (int i = gtid; i < 3 * NSEG; i += gstr) d[i] = 0;
    if (gtid == 0) g_ticket = 0;
}

// ---------------------------------------------------------------------------
// Two-flag lookback over predecessors [first, b): batch-poll 4, consume
// nearest-first, stop at the first INC. Returns exclusive prefix.
template <int PASS>
__device__ __forceinline__ uint32_t lookback(int b, int first, int tid) {
    uint32_t excl = 0;
    int pt = b - 1;
    while (pt >= first) {
        int nb = min(4, pt - first + 1);
        uint32_t v0, v1 = 0, v2 = 0, v3 = 0;
        bool ok;
        do {
            v0 = ld_rlx(&g_status[PASS][pt][tid]);
            if (nb > 1) v1 = ld_rlx(&g_status[PASS][pt - 1][tid]);
            if (nb > 2) v2 = ld_rlx(&g_status[PASS][pt - 2][tid]);
            if (nb > 3) v3 = ld_rlx(&g_status[PASS][pt - 3][tid]);
            ok = (v0 != 0) && (nb < 2 || v1 != 0) &&
                 (nb < 3 || v2 != 0) && (nb < 4 || v3 != 0);
        } while (!ok);
        excl += v0 & CNTMASK;
        if (v0 & INCBIT) return excl;
        if (nb > 1) { excl += v1 & CNTMASK; if (v1 & INCBIT) return excl; }
        if (nb > 2) { excl += v2 & CNTMASK; if (v2 & INCBIT) return excl; }
        if (nb > 3) { excl += v3 & CNTMASK; if (v3 & INCBIT) return excl; }
        pt -= nb;
    }
    return excl;
}

// ---------------------------------------------------------------------------
// One tile of one pass (called from the persistent k_sort).
template <int PASS, bool FUSE>
__device__ __forceinline__ void process_tile(int b,
                                             const float* __restrict__ xin,
                                             const float* __restrict__ init_sorted,
                                             SortSmem& sm) {
    const int s = g_tseg[b];
    const int tid = threadIdx.x, lane = tid & 31, warp = tid >> 5;
    const uint32_t lmask = (1u << lane) - 1u;

    const uint32_t* __restrict__ in =
        (PASS == 1 || PASS == 3) ? g_keyA : g_keyB;   // PASS0 unused
    uint32_t* __restrict__ out = (PASS & 1) ? g_keyB : g_keyA;
    const int shift = 8 * PASS;

    const int beg  = g_off[s], end = g_off[s + 1];
    const int t    = b - g_toff[s];
    const int tbeg = beg + t * TILE;
    const int tend = min(tbeg + TILE, end);
    const int vc   = tend - tbeg;
    const int ntseg = g_toff[s + 1] - g_toff[s];
    const int first = b - t;

    // ---- gate poll (thread 0) overlapped with counter zeroing (rest)
    if (tid == 0) {
        if (PASS > 0)
            while (ld_acq(&g_segdone[PASS - 1][s]) < (uint32_t)ntseg)
                __nanosleep(64);
    } else {
        for (int i = tid - 1; i < 256 * 17; i += NT - 1)
            ((uint32_t*)sm.cnt)[i] = 0;
    }
    __syncthreads();

    uint32_t keys[IT];
    uint32_t rnkp[IT / 2] = {0, 0, 0, 0};   // 2 x u16 ranks per word
    const int ibase = tbeg + warp * (IT * 32) + lane;

    if (vc == TILE) {
        // -------- fast path: every item valid
#pragma unroll
        for (int j = 0; j < IT; j++) {
            int idx = ibase + j * 32;
            keys[j] = (PASS == 0) ? flipf(__float_as_uint(xin[idx])) : in[idx];
        }
#pragma unroll
        for (int j = 0; j < IT; j++) {
            uint32_t d = (keys[j] >> shift) & 255u;
            uint32_t m = __match_any_sync(FULLMASK, d);
            int lead = __ffs(m) - 1;
            uint32_t cur = 0;
            if (lane == lead) {
                cur = sm.cnt[d][warp];
                sm.cnt[d][warp] = cur + (uint32_t)__popc(m);
            }
            cur = __shfl_sync(FULLMASK, cur, lead);
            rnkp[j >> 1] |= (cur + (uint32_t)__popc(m & lmask)) << (16 * (j & 1));
            __syncwarp();
        }
    } else {
        // -------- tail tile: masked
#pragma unroll
        for (int j = 0; j < IT; j++) {
            int idx = ibase + j * 32;
            bool valid = idx < tend;
            keys[j] = valid ? ((PASS == 0) ? flipf(__float_as_uint(xin[idx]))
                                           : in[idx])
                            : 0u;
        }
#pragma unroll
        for (int j = 0; j < IT; j++) {
            bool valid = (ibase + j * 32) < tend;
            uint32_t d = (keys[j] >> shift) & 255u;
            uint32_t vm = __ballot_sync(FULLMASK, valid);
            uint32_t m  = __match_any_sync(FULLMASK, d) & vm;
            int lead = m ? (__ffs(m) - 1) : 0;
            uint32_t cur = 0;
            if (valid && lane == lead) {
                cur = sm.cnt[d][warp];
                sm.cnt[d][warp] = cur + (uint32_t)__popc(m);
            }
            cur = __shfl_sync(FULLMASK, cur, lead);
            rnkp[j >> 1] |= (cur + (uint32_t)__popc(m & lmask)) << (16 * (j & 1));
            __syncwarp();
        }
    }
    __syncthreads();

    // ---- per-digit warp totals -> warp-exclusive in place; publish AGG
    uint32_t tot = 0;
    if (tid < 256) {
        uint32_t run = 0;
#pragma unroll
        for (int w = 0; w < NWARP; w++) {
            uint32_t c = sm.cnt[tid][w];
            sm.cnt[tid][w] = run;
            run += c;
        }
        tot = run;
        st_rlx(&g_status[PASS][b][tid], tot | AGGBIT);   // unblock successors
    }

    // ---- tile-local digit starts
    uint32_t loc = scan256(tot, tid, sm.wsum);

    // ---- lookback (doubles as this pass's segment-histogram aggregation)
    uint32_t excl = 0;
    if (tid < 256) {
        excl = lookback<PASS>(b, first, tid);
        st_rlx(&g_status[PASS][b][tid], (excl + tot) | INCBIT);
    }

    // ---- segment histogram: last tile owns tot+excl; peers wait for it
    uint32_t hval = 0;
    if (t == ntseg - 1) {
        if (tid < 256) {
            hval = tot + excl;
            g_hist[PASS][s][tid] = hval;
        }
        __syncthreads();                    // all hist writes done
        if (tid == 0) red_release(&g_histdone[PASS][s], 1u);
    } else {
        if (tid == 0)
            while (ld_acq(&g_histdone[PASS][s]) == 0) __nanosleep(64);
        __syncthreads();
        if (tid < 256) hval = g_hist[PASS][s][tid];
    }
    uint32_t segx = scan256(hval, tid, sm.wsum);

    if (tid < 256) {
        sm.loc[tid] = loc;
        sm.fix[tid] = (uint32_t)beg + segx + excl - loc;
    }
    __syncthreads();

    // ---- scatter to smem exchange by tile-local rank
#pragma unroll
    for (int j = 0; j < IT; j++) {
        int idx = ibase + j * 32;
        if (idx < tend) {
            uint32_t d = (keys[j] >> shift) & 255u;
            uint32_t r = (rnkp[j >> 1] >> (16 * (j & 1))) & 0xffffu;
            sm.exch[sm.loc[d] + sm.cnt[d][warp] + r] = keys[j];
        }
    }
    __syncthreads();

    // ---- writeout: pure coalesced pass (no histogram, no atomics)
    float acc = 0.f;
#pragma unroll
    for (int j = 0; j < IT; j++) {
        int p = j * NT + tid;
        if (p < vc) {
            uint32_t k = sm.exch[p];
            uint32_t d = (k >> shift) & 255u;
            uint32_t g = sm.fix[d] + (uint32_t)p;
            if (FUSE) acc += fabsf(unflip(k) - init_sorted[g]);
            else      out[g] = k;
        }
    }

    if (PASS < 3) {
        __syncthreads();   // orders block's key writes before release-add
        if (tid == 0) red_release(&g_segdone[PASS][s], 1u);
    }

    if (FUSE) {
#pragma unroll
        for (int o = 16; o; o >>= 1) acc += __shfl_down_sync(FULLMASK, acc, o);
        if (lane == 0) sm.red[warp] = acc;
        __syncthreads();
        if (warp == 0) {
            float v = (lane < NWARP) ? sm.red[lane] : 0.f;
#pragma unroll
            for (int o = 8; o; o >>= 1) v += __shfl_down_sync(FULLMASK, v, o);
            if (lane == 0) g_part[b] = v;
        }
    }
}

// ---------------------------------------------------------------------------
// Persistent driver: pass-major tickets. Dependencies: lookback preds and
// prev-pass segdone are strictly-earlier tickets; the histdone wait targets
// the segment's LAST tile, <= +10 tickets ahead -- always inside the
// 444-ticket in-flight window, and that tile never waits on histdone itself
// (it publishes), so forward progress is guaranteed.
__global__ __launch_bounds__(NT, 3) void k_sort(const float* __restrict__ x,
                                                const float* __restrict__ init) {
    __shared__ SortSmem sm;
    const int ntile = g_toff[NSEG];
    const int ntk   = 4 * ntile;
    for (;;) {
        if (threadIdx.x == 0) sm.tk = (int)atomicAdd(&g_ticket, 1u);
        __syncthreads();
        const int tk = sm.tk;
        if (tk >= ntk) return;
        const int pass = tk / ntile;
        const int b    = tk - pass * ntile;
        switch (pass) {
            case 0:  process_tile<0, false>(b, x, init, sm); break;
            case 1:  process_tile<1, false>(b, x, init, sm); break;
            case 2:  process_tile<2, false>(b, x, init, sm); break;
            default: process_tile<3, true >(b, x, init, sm); break;
        }
    }
}

// ---------------------------------------------------------------------------
__global__ void k_final(float* __restrict__ outp) {
    __shared__ float sh[256];
    int tid = threadIdx.x;
    float v = 0.f;
    if (tid < NSEG) {
        int len = g_off[tid + 1] - g_off[tid];
        float sum = 0.f;
        for (int t = g_toff[tid]; t < g_toff[tid + 1]; t++) sum += g_part[t];
        v = (len > 0) ? sum / (float)len : 0.f;
    }
    sh[tid] = v;
    __syncthreads();
    for (int o = 128; o; o >>= 1) {
        if (tid < o) sh[tid] += sh[tid + o];
        __syncthreads();
    }
    if (tid == 0) outp[0] = sh[0] * (1e-3f / (float)NSEG);
}

// ---------------------------------------------------------------------------
extern "C" void kernel_launch(void* const* d_in, const int* in_sizes, int n_in,
                              void* d_out, int out_size) {
    const float* x    = (const float*)d_in[0];
    const float* init = (const float*)d_in[1];
    const int*   seg  = (const int*)d_in[2];
    int n = in_sizes[0];

    k_setup<<<1, 256>>>(seg, n);
    k_zero<<<512, 512>>>();
    k_sort<<<GRIDSORT, NT>>>(x, init);
    k_final<<<1, 256>>>((float*)d_out);
}

// round 16
// speedup vs baseline: 1.1520x; 1.1520x over previous
#include <cuda_runtime.h>
#include <stdint.h>

// EarthMoversDistanceRegularizer v14: v11 (best measured, 324us) byte-identical
// except the single isolated variable: __launch_bounds__(512,4) + GRIDSORT 592
// (4 CTAs/SM = 64 warps, forcing regs <= 32). Occupancy experiment.

#define NSEG     200
#define NMAX     8388608
#define NT       512
#define NWARP    16
#define IT       8
#define TILE     (NT * IT)              // 4096
#define MAXT     2304                   // >= NMAX/TILE + NSEG = 2248
#define GRIDSORT 592                    // 148 SMs x 4 CTAs
#define FULLMASK 0xffffffffu
#define FLAGBIT  (1u << 30)
#define CNTMASK  0x3fffffffu

__device__ uint32_t g_keyA[NMAX];
__device__ uint32_t g_keyB[NMAX];
__device__ int      g_off[NSEG + 1];
__device__ int      g_toff[NSEG + 1];
__device__ int      g_tseg[MAXT];
__device__ uint32_t g_hist[NSEG][4][256];
__device__ uint32_t g_status[4][MAXT][256];
__device__ uint32_t g_histdone[NSEG];
__device__ uint32_t g_segdone[3][NSEG];
__device__ uint32_t g_ticket;
__device__ float    g_part[MAXT];

__device__ __forceinline__ uint32_t flipf(uint32_t u) {
    return (u & 0x80000000u) ? ~u : (u | 0x80000000u);
}
__device__ __forceinline__ float unflip(uint32_t k) {
    uint32_t u = (k & 0x80000000u) ? (k & 0x7fffffffu) : ~k;
    return __uint_as_float(u);
}
__device__ __forceinline__ void st_rlx(uint32_t* p, uint32_t v) {
    asm volatile("st.relaxed.gpu.u32 [%0], %1;" :: "l"(p), "r"(v) : "memory");
}
__device__ __forceinline__ uint32_t ld_rlx(const uint32_t* p) {
    uint32_t v;
    asm volatile("ld.relaxed.gpu.u32 %0, [%1];" : "=r"(v) : "l"(p) : "memory");
    return v;
}
__device__ __forceinline__ uint32_t ld_acq(const uint32_t* p) {
    uint32_t v;
    asm volatile("ld.acquire.gpu.u32 %0, [%1];" : "=r"(v) : "l"(p) : "memory");
    return v;
}
// Release add (no return); preceded by __syncthreads it publishes the whole
// block's prior writes to a paired acquire reader.
__device__ __forceinline__ void red_release(uint32_t* p, uint32_t v) {
    asm volatile("red.release.gpu.global.add.u32 [%0], %1;" :: "l"(p), "r"(v)
                 : "memory");
}

struct SortSmem {
    uint32_t cnt[256][17];   // padded: conflict-free rank atomics + scan
    uint32_t exch[TILE];
    uint32_t loc[256];
    uint32_t fix[256];
    uint32_t wsum[8];
    uint32_t h[8][257];      // lane-spread replicas, 8 distinct banks
    float    red[NWARP];
    int      tk;
};

// ---------------------------------------------------------------------------
// Exclusive prefix over values held by threads 0..255 (others pass 0).
__device__ __forceinline__ uint32_t scan256(uint32_t v, int tid, uint32_t* s_wsum) {
    int lane = tid & 31, w = tid >> 5;
    uint32_t inc = v;
#pragma unroll
    for (int o = 1; o < 32; o <<= 1) {
        uint32_t t = __shfl_up_sync(FULLMASK, inc, o);
        if (lane >= o) inc += t;
    }
    if (lane == 31 && w < 8) s_wsum[w] = inc;
    __syncthreads();
    if (w == 0 && lane < 8) {
        uint32_t x0 = s_wsum[lane];
        uint32_t i2 = x0;
#pragma unroll
        for (int o = 1; o < 8; o <<= 1) {
            uint32_t t = __shfl_up_sync(0xffu, i2, o);
            if (lane >= o) i2 += t;
        }
        s_wsum[lane] = i2 - x0;
    }
    __syncthreads();
    return inc - v + ((tid < 256) ? s_wsum[w] : 0u);
}

// ---------------------------------------------------------------------------
__global__ void k_setup(const int* __restrict__ seg, int n) {
    __shared__ uint32_t s_wsum[8];
    int tid = threadIdx.x;
    if (tid <= NSEG) {
        int lo = 0, hi = n;
        while (lo < hi) {
            int mid = (lo + hi) >> 1;
            if (seg[mid] < tid) lo = mid + 1; else hi = mid;
        }
        g_off[tid] = lo;
    }
    __syncthreads();
    uint32_t nt = 0;
    if (tid < NSEG) {
        int len = g_off[tid + 1] - g_off[tid];
        nt = (uint32_t)((len + TILE - 1) / TILE);
    }
    uint32_t excl = scan256(nt, tid, s_wsum);
    if (tid <= NSEG) g_toff[tid] = (int)excl;
    for (int t = tid; t < MAXT; t += 256) g_tseg[t] = -1;
    __syncthreads();
    if (tid < NSEG)
        for (uint32_t t = 0; t < nt; t++) g_tseg[excl + t] = tid;
}

// ---------------------------------------------------------------------------
__global__ void k_zero() {
    const int gtid = blockIdx.x * blockDim.x + threadIdx.x;
    const int gstr = gridDim.x * blockDim.x;
    uint32_t* p = &g_status[0][0][0];
    for (int i = gtid; i < 4 * MAXT * 256; i += gstr) p[i] = 0;
    uint32_t* h = &g_hist[0][0][0];
    for (int i = gtid; i < NSEG * 4 * 256; i += gstr) h[i] = 0;
    uint32_t* d = &g_segdone[0][0];
    for (int i = gtid; i < 3 * NSEG; i += gstr) d[i] = 0;
    for (int i = gtid; i < NSEG; i += gstr) g_histdone[i] = 0;
    if (gtid == 0) g_ticket = 0;
}

// ---------------------------------------------------------------------------
// One tile of one pass (called from the persistent k_sort).
template <int PASS, bool FUSE>
__device__ __forceinline__ void process_tile(int b,
                                             const float* __restrict__ xin,
                                             const float* __restrict__ init_sorted,
                                             SortSmem& sm) {
    const int s = g_tseg[b];
    const int tid = threadIdx.x, lane = tid & 31, warp = tid >> 5;
    const uint32_t lmask = (1u << lane) - 1u;

    const uint32_t* __restrict__ in =
        (PASS == 1 || PASS == 3) ? g_keyA : g_keyB;   // PASS0 unused
    uint32_t* __restrict__ out = (PASS & 1) ? g_keyB : g_keyA;
    const int shift = 8 * PASS;

    const int beg  = g_off[s], end = g_off[s + 1];
    const int t    = b - g_toff[s];
    const int tbeg = beg + t * TILE;
    const int tend = min(tbeg + TILE, end);
    const int vc   = tend - tbeg;
    const int ntseg = g_toff[s + 1] - g_toff[s];

    // ---- gate: previous pass of this segment must be fully complete
    //      (pass 0 has no gate: its histogram comes from its own lookback)
    if (PASS > 0) {
        if (tid == 0) {
            while (ld_acq(&g_segdone[PASS - 1][s]) < (uint32_t)ntseg)
                __nanosleep(64);
        }
        __syncthreads();
    }

    for (int i = tid; i < 256 * 17; i += NT) ((uint32_t*)sm.cnt)[i] = 0;
    if (PASS < 3)
        for (int i = tid; i < 8 * 257; i += NT) ((uint32_t*)sm.h)[i] = 0;
    __syncthreads();

    uint32_t keys[IT];
    uint32_t rnkp[IT / 2] = {0, 0, 0, 0};   // 2 x u16 ranks per word
    const int ibase = tbeg + warp * (IT * 32) + lane;

    if (vc == TILE) {
        // -------- fast path: every item valid
#pragma unroll
        for (int j = 0; j < IT; j++) {
            int idx = ibase + j * 32;
            keys[j] = (PASS == 0) ? flipf(__float_as_uint(xin[idx])) : in[idx];
        }
#pragma unroll
        for (int j = 0; j < IT; j++) {
            uint32_t d = (keys[j] >> shift) & 255u;
            uint32_t m = __match_any_sync(FULLMASK, d);
            int lead = __ffs(m) - 1;
            uint32_t cur = 0;
            if (lane == lead) cur = atomicAdd(&sm.cnt[d][warp], (uint32_t)__popc(m));
            cur = __shfl_sync(FULLMASK, cur, lead);
            rnkp[j >> 1] |= (cur + (uint32_t)__popc(m & lmask)) << (16 * (j & 1));
        }
    } else {
        // -------- tail tile: masked
#pragma unroll
        for (int j = 0; j < IT; j++) {
            int idx = ibase + j * 32;
            bool valid = idx < tend;
            keys[j] = valid ? ((PASS == 0) ? flipf(__float_as_uint(xin[idx]))
                                           : in[idx])
                            : 0u;
        }
#pragma unroll
        for (int j = 0; j < IT; j++) {
            bool valid = (ibase + j * 32) < tend;
            uint32_t d = (keys[j] >> shift) & 255u;
            uint32_t vm = __ballot_sync(FULLMASK, valid);
            uint32_t m  = __match_any_sync(FULLMASK, d) & vm;
            int lead = m ? (__ffs(m) - 1) : 0;
            uint32_t cur = 0;
            if (valid && lane == lead)
                cur = atomicAdd(&sm.cnt[d][warp], (uint32_t)__popc(m));
            cur = __shfl_sync(FULLMASK, cur, lead);
            rnkp[j >> 1] |= (cur + (uint32_t)__popc(m & lmask)) << (16 * (j & 1));
        }
    }
    __syncthreads();

    // ---- per-digit warp totals -> warp-exclusive in place; publish count
    uint32_t tot = 0;
    if (tid < 256) {
        uint32_t run = 0;
#pragma unroll
        for (int w = 0; w < NWARP; w++) {
            uint32_t c = sm.cnt[tid][w];
            sm.cnt[tid][w] = run;
            run += c;
        }
        tot = run;
        st_rlx(&g_status[PASS][b][tid], tot | FLAGBIT);   // unblock successors
    }

    uint32_t loc, segx, excl = 0;

    if (PASS == 0) {
        // ---- tile-local digit starts
        loc = scan256(tot, tid, sm.wsum);

        // ---- lookback (also aggregates the segment histogram)
        if (tid < 256) {
            int pt = b - 1;
            const int first = b - t;
            while (pt >= first) {
                int nb = min(4, pt - first + 1);
                uint32_t v0, v1 = 0, v2 = 0, v3 = 0;
                bool ok;
                do {
                    v0 = ld_rlx(&g_status[0][pt][tid]);
                    if (nb > 1) v1 = ld_rlx(&g_status[0][pt - 1][tid]);
                    if (nb > 2) v2 = ld_rlx(&g_status[0][pt - 2][tid]);
                    if (nb > 3) v3 = ld_rlx(&g_status[0][pt - 3][tid]);
                    ok = (v0 != 0) && (nb < 2 || v1 != 0) &&
                         (nb < 3 || v2 != 0) && (nb < 4 || v3 != 0);
                } while (!ok);
                excl += (v0 & CNTMASK) + (v1 & CNTMASK) +
                        (v2 & CNTMASK) + (v3 & CNTMASK);
                pt -= nb;
            }
        }

        // ---- last tile of the segment owns the totals: tot + excl summed
        //      over all tiles == full segment pass-0 histogram
        if (t == ntseg - 1) {
            if (tid < 256) g_hist[s][0][tid] = tot + excl;
            __syncthreads();                    // all writes done
            if (tid == 0) red_release(&g_histdone[s], 1u);
        } else {
            if (tid == 0)
                while (ld_acq(&g_histdone[s]) == 0) __nanosleep(64);
            __syncthreads();
        }

        // ---- segment digit bases
        uint32_t h = (tid < 256) ? g_hist[s][0][tid] : 0u;
        segx = scan256(h, tid, sm.wsum);
    } else {
        // ---- packed scan: hi16 = tile-local start, lo16 = segment base
        uint32_t h = (tid < 256) ? g_hist[s][PASS][tid] : 0u;
        uint32_t px = scan256((tot << 16) | h, tid, sm.wsum);
        loc  = px >> 16;
        segx = px & 0xffffu;

        // ---- AGG-only lookback, 4-wide MLP batches
        if (tid < 256) {
            int pt = b - 1;
            const int first = b - t;
            while (pt >= first) {
                int nb = min(4, pt - first + 1);
                uint32_t v0, v1 = 0, v2 = 0, v3 = 0;
                bool ok;
                do {
                    v0 = ld_rlx(&g_status[PASS][pt][tid]);
                    if (nb > 1) v1 = ld_rlx(&g_status[PASS][pt - 1][tid]);
                    if (nb > 2) v2 = ld_rlx(&g_status[PASS][pt - 2][tid]);
                    if (nb > 3) v3 = ld_rlx(&g_status[PASS][pt - 3][tid]);
                    ok = (v0 != 0) && (nb < 2 || v1 != 0) &&
                         (nb < 3 || v2 != 0) && (nb < 4 || v3 != 0);
                } while (!ok);
                excl += (v0 & CNTMASK) + (v1 & CNTMASK) +
                        (v2 & CNTMASK) + (v3 & CNTMASK);
                pt -= nb;
            }
        }
    }

    if (tid < 256) {
        sm.loc[tid] = loc;
        sm.fix[tid] = (uint32_t)beg + segx + excl - loc;
    }
    __syncthreads();

    // ---- scatter to smem exchange by tile-local rank
#pragma unroll
    for (int j = 0; j < IT; j++) {
        int idx = ibase + j * 32;
        if (idx < tend) {
            uint32_t d = (keys[j] >> shift) & 255u;
            uint32_t r = (rnkp[j >> 1] >> (16 * (j & 1))) & 0xffffu;
            sm.exch[sm.loc[d] + sm.cnt[d][warp] + r] = keys[j];
        }
    }
    __syncthreads();

    // ---- coalesced global pass; inline next-pass histogram (lane-spread)
    float acc = 0.f;
#pragma unroll
    for (int j = 0; j < IT; j++) {
        int p = j * NT + tid;
        if (p < vc) {
            uint32_t k = sm.exch[p];
            uint32_t d = (k >> shift) & 255u;
            uint32_t g = sm.fix[d] + (uint32_t)p;
            if (PASS < 3)
                atomicAdd(&sm.h[lane & 7][(k >> (shift + 8)) & 255u], 1u);
            if (FUSE) acc += fabsf(unflip(k) - init_sorted[g]);
            else      out[g] = k;
        }
    }

    if (PASS < 3) {
        __syncthreads();
        if (tid < 256) {
            uint32_t v = 0;
#pragma unroll
            for (int r = 0; r < 8; r++) v += sm.h[r][tid];
            if (v) atomicAdd(&g_hist[s][PASS + 1][tid], v);
        }
        __syncthreads();   // orders block's writes before release-add
        if (tid == 0) red_release(&g_segdone[PASS][s], 1u);
    }

    if (FUSE) {
#pragma unroll
        for (int o = 16; o; o >>= 1) acc += __shfl_down_sync(FULLMASK, acc, o);
        if (lane == 0) sm.red[warp] = acc;
        __syncthreads();
        if (warp == 0) {
            float v = (lane < NWARP) ? sm.red[lane] : 0.f;
#pragma unroll
            for (int o = 8; o; o >>= 1) v += __shfl_down_sync(FULLMASK, v, o);
            if (lane == 0) g_part[b] = v;
        }
    }
}

// ---------------------------------------------------------------------------
// Persistent driver: pass-major tickets (4 passes, no histogram phase).
// All dependencies are earlier-or-nearby tickets held by resident CTAs
// (lookback: earlier; pass-0 hist aggregation: within +ntiles(s) <= +11,
// far inside the in-flight window) -> guaranteed forward progress.
__global__ __launch_bounds__(NT, 4) void k_sort(const float* __restrict__ x,
                                                const float* __restrict__ init) {
    __shared__ SortSmem sm;
    const int ntile = g_toff[NSEG];
    const int ntk   = 4 * ntile;
    for (;;) {
        if (threadIdx.x == 0) sm.tk = (int)atomicAdd(&g_ticket, 1u);
        __syncthreads();
        const int tk = sm.tk;
        if (tk >= ntk) return;
        const int pass = tk / ntile;
        const int b    = tk - pass * ntile;
        switch (pass) {
            case 0:  process_tile<0, false>(b, x, init, sm); break;
            case 1:  process_tile<1, false>(b, x, init, sm); break;
            case 2:  process_tile<2, false>(b, x, init, sm); break;
            default: process_tile<3, true >(b, x, init, sm); break;
        }
        __syncthreads();   // protect sm reuse across tickets
    }
}

// ---------------------------------------------------------------------------
__global__ void k_final(float* __restrict__ outp) {
    __shared__ float sh[256];
    int tid = threadIdx.x;
    float v = 0.f;
    if (tid < NSEG) {
        int len = g_off[tid + 1] - g_off[tid];
        float sum = 0.f;
        for (int t = g_toff[tid]; t < g_toff[tid + 1]; t++) sum += g_part[t];
        v = (len > 0) ? sum / (float)len : 0.f;
    }
    sh[tid] = v;
    __syncthreads();
    for (int o = 128; o; o >>= 1) {
        if (tid < o) sh[tid] += sh[tid + o];
        __syncthreads();
    }
    if (tid == 0) outp[0] = sh[0] * (1e-3f / (float)NSEG);
}

// ---------------------------------------------------------------------------
extern "C" void kernel_launch(void* const* d_in, const int* in_sizes, int n_in,
                              void* d_out, int out_size) {
    const float* x    = (const float*)d_in[0];
    const float* init = (const float*)d_in[1];
    const int*   seg  = (const int*)d_in[2];
    int n = in_sizes[0];

    k_setup<<<1, 256>>>(seg, n);
    k_zero<<<512, 512>>>();
    k_sort<<<GRIDSORT, NT>>>(x, init);
    k_final<<<1, 256>>>((float*)d_out);
}

// round 17
// speedup vs baseline: 1.1834x; 1.0272x over previous
#include <cuda_runtime.h>
#include <stdint.h>

// EarthMoversDistanceRegularizer v15: v14 algorithm with NT=256 / 8 CTAs/SM.
// Same 64 warps/SM, but every 256-wide serial phase (totals/scan/lookback)
// now uses ALL threads of the CTA (no idle half-block), and 8 independent
// CTAs interleave across barrier/poll phases. TILE 2048, IT 8, NWARP 8.

#define NSEG     200
#define NMAX     8388608
#define NT       256
#define NWARP    8
#define IT       8
#define TILE     (NT * IT)              // 2048
#define MAXT     4296                   // >= NMAX/TILE + NSEG = 4296
#define GRIDSORT 1184                   // 148 SMs x 8 CTAs
#define FULLMASK 0xffffffffu
#define FLAGBIT  (1u << 30)
#define CNTMASK  0x3fffffffu

__device__ uint32_t g_keyA[NMAX];
__device__ uint32_t g_keyB[NMAX];
__device__ int      g_off[NSEG + 1];
__device__ int      g_toff[NSEG + 1];
__device__ int      g_tseg[MAXT];
__device__ uint32_t g_hist[NSEG][4][256];
__device__ uint32_t g_status[4][MAXT][256];
__device__ uint32_t g_histdone[NSEG];
__device__ uint32_t g_segdone[3][NSEG];
__device__ uint32_t g_ticket;
__device__ float    g_part[MAXT];

__device__ __forceinline__ uint32_t flipf(uint32_t u) {
    return (u & 0x80000000u) ? ~u : (u | 0x80000000u);
}
__device__ __forceinline__ float unflip(uint32_t k) {
    uint32_t u = (k & 0x80000000u) ? (k & 0x7fffffffu) : ~k;
    return __uint_as_float(u);
}
__device__ __forceinline__ void st_rlx(uint32_t* p, uint32_t v) {
    asm volatile("st.relaxed.gpu.u32 [%0], %1;" :: "l"(p), "r"(v) : "memory");
}
__device__ __forceinline__ uint32_t ld_rlx(const uint32_t* p) {
    uint32_t v;
    asm volatile("ld.relaxed.gpu.u32 %0, [%1];" : "=r"(v) : "l"(p) : "memory");
    return v;
}
__device__ __forceinline__ uint32_t ld_acq(const uint32_t* p) {
    uint32_t v;
    asm volatile("ld.acquire.gpu.u32 %0, [%1];" : "=r"(v) : "l"(p) : "memory");
    return v;
}
// Release add (no return); preceded by __syncthreads it publishes the whole
// block's prior writes to a paired acquire reader.
__device__ __forceinline__ void red_release(uint32_t* p, uint32_t v) {
    asm volatile("red.release.gpu.global.add.u32 [%0], %1;" :: "l"(p), "r"(v)
                 : "memory");
}

struct SortSmem {
    uint32_t cnt[256][NWARP + 1];  // padded: conflict-free rank atomics + scan
    uint32_t exch[TILE];
    uint32_t loc[256];
    uint32_t fix[256];
    uint32_t wsum[8];
    uint32_t h[4][257];            // lane-spread replicas, distinct banks
    float    red[NWARP];
    int      tk;
};

// ---------------------------------------------------------------------------
// Exclusive prefix over 256 values held by the 256 threads (NT == 256).
__device__ __forceinline__ uint32_t scan256(uint32_t v, int tid, uint32_t* s_wsum) {
    int lane = tid & 31, w = tid >> 5;
    uint32_t inc = v;
#pragma unroll
    for (int o = 1; o < 32; o <<= 1) {
        uint32_t t = __shfl_up_sync(FULLMASK, inc, o);
        if (lane >= o) inc += t;
    }
    if (lane == 31) s_wsum[w] = inc;
    __syncthreads();
    if (w == 0 && lane < 8) {
        uint32_t x0 = s_wsum[lane];
        uint32_t i2 = x0;
#pragma unroll
        for (int o = 1; o < 8; o <<= 1) {
            uint32_t t = __shfl_up_sync(0xffu, i2, o);
            if (lane >= o) i2 += t;
        }
        s_wsum[lane] = i2 - x0;
    }
    __syncthreads();
    return inc - v + s_wsum[w];
}

// ---------------------------------------------------------------------------
__global__ void k_setup(const int* __restrict__ seg, int n) {
    __shared__ uint32_t s_wsum[8];
    int tid = threadIdx.x;
    if (tid <= NSEG) {
        int lo = 0, hi = n;
        while (lo < hi) {
            int mid = (lo + hi) >> 1;
            if (seg[mid] < tid) lo = mid + 1; else hi = mid;
        }
        g_off[tid] = lo;
    }
    __syncthreads();
    uint32_t nt = 0;
    if (tid < NSEG) {
        int len = g_off[tid + 1] - g_off[tid];
        nt = (uint32_t)((len + TILE - 1) / TILE);
    }
    uint32_t excl = scan256(nt, tid, s_wsum);
    if (tid <= NSEG) g_toff[tid] = (int)excl;
    for (int t = tid; t < MAXT; t += 256) g_tseg[t] = -1;
    __syncthreads();
    if (tid < NSEG)
        for (uint32_t t = 0; t < nt; t++) g_tseg[excl + t] = tid;
}

// ---------------------------------------------------------------------------
__global__ void k_zero() {
    const int gtid = blockIdx.x * blockDim.x + threadIdx.x;
    const int gstr = gridDim.x * blockDim.x;
    uint32_t* p = &g_status[0][0][0];
    for (int i = gtid; i < 4 * MAXT * 256; i += gstr) p[i] = 0;
    uint32_t* h = &g_hist[0][0][0];
    for (int i = gtid; i < NSEG * 4 * 256; i += gstr) h[i] = 0;
    uint32_t* d = &g_segdone[0][0];
    for (int i = gtid; i < 3 * NSEG; i += gstr) d[i] = 0;
    for (int i = gtid; i < NSEG; i += gstr) g_histdone[i] = 0;
    if (gtid == 0) g_ticket = 0;
}

// ---------------------------------------------------------------------------
// One tile of one pass (called from the persistent k_sort).
template <int PASS, bool FUSE>
__device__ __forceinline__ void process_tile(int b,
                                             const float* __restrict__ xin,
                                             const float* __restrict__ init_sorted,
                                             SortSmem& sm) {
    const int s = g_tseg[b];
    const int tid = threadIdx.x, lane = tid & 31, warp = tid >> 5;
    const uint32_t lmask = (1u << lane) - 1u;

    const uint32_t* __restrict__ in =
        (PASS == 1 || PASS == 3) ? g_keyA : g_keyB;   // PASS0 unused
    uint32_t* __restrict__ out = (PASS & 1) ? g_keyB : g_keyA;
    const int shift = 8 * PASS;

    const int beg  = g_off[s], end = g_off[s + 1];
    const int t    = b - g_toff[s];
    const int tbeg = beg + t * TILE;
    const int tend = min(tbeg + TILE, end);
    const int vc   = tend - tbeg;
    const int ntseg = g_toff[s + 1] - g_toff[s];

    // ---- gate: previous pass of this segment must be fully complete
    //      (pass 0 has no gate: its histogram comes from its own lookback)
    if (PASS > 0) {
        if (tid == 0) {
            while (ld_acq(&g_segdone[PASS - 1][s]) < (uint32_t)ntseg)
                __nanosleep(64);
        }
        __syncthreads();
    }

    for (int i = tid; i < 256 * (NWARP + 1); i += NT) ((uint32_t*)sm.cnt)[i] = 0;
    if (PASS < 3)
        for (int i = tid; i < 4 * 257; i += NT) ((uint32_t*)sm.h)[i] = 0;
    __syncthreads();

    uint32_t keys[IT];
    uint32_t rnkp[IT / 2] = {0, 0, 0, 0};   // 2 x u16 ranks per word
    const int ibase = tbeg + warp * (IT * 32) + lane;

    if (vc == TILE) {
        // -------- fast path: every item valid
#pragma unroll
        for (int j = 0; j < IT; j++) {
            int idx = ibase + j * 32;
            keys[j] = (PASS == 0) ? flipf(__float_as_uint(xin[idx])) : in[idx];
        }
#pragma unroll
        for (int j = 0; j < IT; j++) {
            uint32_t d = (keys[j] >> shift) & 255u;
            uint32_t m = __match_any_sync(FULLMASK, d);
            int lead = __ffs(m) - 1;
            uint32_t cur = 0;
            if (lane == lead) cur = atomicAdd(&sm.cnt[d][warp], (uint32_t)__popc(m));
            cur = __shfl_sync(FULLMASK, cur, lead);
            rnkp[j >> 1] |= (cur + (uint32_t)__popc(m & lmask)) << (16 * (j & 1));
        }
    } else {
        // -------- tail tile: masked
#pragma unroll
        for (int j = 0; j < IT; j++) {
            int idx = ibase + j * 32;
            bool valid = idx < tend;
            keys[j] = valid ? ((PASS == 0) ? flipf(__float_as_uint(xin[idx]))
                                           : in[idx])
                            : 0u;
        }
#pragma unroll
        for (int j = 0; j < IT; j++) {
            bool valid = (ibase + j * 32) < tend;
            uint32_t d = (keys[j] >> shift) & 255u;
            uint32_t vm = __ballot_sync(FULLMASK, valid);
            uint32_t m  = __match_any_sync(FULLMASK, d) & vm;
            int lead = m ? (__ffs(m) - 1) : 0;
            uint32_t cur = 0;
            if (valid && lane == lead)
                cur = atomicAdd(&sm.cnt[d][warp], (uint32_t)__popc(m));
            cur = __shfl_sync(FULLMASK, cur, lead);
            rnkp[j >> 1] |= (cur + (uint32_t)__popc(m & lmask)) << (16 * (j & 1));
        }
    }
    __syncthreads();

    // ---- per-digit warp totals -> warp-exclusive in place; publish count
    uint32_t tot;
    {
        uint32_t run = 0;
#pragma unroll
        for (int w = 0; w < NWARP; w++) {
            uint32_t c = sm.cnt[tid][w];
            sm.cnt[tid][w] = run;
            run += c;
        }
        tot = run;
        st_rlx(&g_status[PASS][b][tid], tot | FLAGBIT);   // unblock successors
    }

    uint32_t loc, segx, excl = 0;

    if (PASS == 0) {
        // ---- tile-local digit starts
        loc = scan256(tot, tid, sm.wsum);

        // ---- lookback (also aggregates the segment histogram)
        {
            int pt = b - 1;
            const int first = b - t;
            while (pt >= first) {
                int nb = min(4, pt - first + 1);
                uint32_t v0, v1 = 0, v2 = 0, v3 = 0;
                bool ok;
                do {
                    v0 = ld_rlx(&g_status[0][pt][tid]);
                    if (nb > 1) v1 = ld_rlx(&g_status[0][pt - 1][tid]);
                    if (nb > 2) v2 = ld_rlx(&g_status[0][pt - 2][tid]);
                    if (nb > 3) v3 = ld_rlx(&g_status[0][pt - 3][tid]);
                    ok = (v0 != 0) && (nb < 2 || v1 != 0) &&
                         (nb < 3 || v2 != 0) && (nb < 4 || v3 != 0);
                } while (!ok);
                excl += (v0 & CNTMASK) + (v1 & CNTMASK) +
                        (v2 & CNTMASK) + (v3 & CNTMASK);
                pt -= nb;
            }
        }

        // ---- last tile of the segment owns the totals: tot + excl summed
        //      over all tiles == full segment pass-0 histogram
        if (t == ntseg - 1) {
            g_hist[s][0][tid] = tot + excl;
            __syncthreads();                    // all writes done
            if (tid == 0) red_release(&g_histdone[s], 1u);
        } else {
            if (tid == 0)
                while (ld_acq(&g_histdone[s]) == 0) __nanosleep(64);
            __syncthreads();
        }

        // ---- segment digit bases
        segx = scan256(g_hist[s][0][tid], tid, sm.wsum);
    } else {
        // ---- packed scan: hi16 = tile-local start (<=2048), lo16 = segment
        //      base (< 65536): no carry between halves
        uint32_t px = scan256((tot << 16) | g_hist[s][PASS][tid], tid, sm.wsum);
        loc  = px >> 16;
        segx = px & 0xffffu;

        // ---- AGG-only lookback, 4-wide MLP batches
        {
            int pt = b - 1;
            const int first = b - t;
            while (pt >= first) {
                int nb = min(4, pt - first + 1);
                uint32_t v0, v1 = 0, v2 = 0, v3 = 0;
                bool ok;
                do {
                    v0 = ld_rlx(&g_status[PASS][pt][tid]);
                    if (nb > 1) v1 = ld_rlx(&g_status[PASS][pt - 1][tid]);
                    if (nb > 2) v2 = ld_rlx(&g_status[PASS][pt - 2][tid]);
                    if (nb > 3) v3 = ld_rlx(&g_status[PASS][pt - 3][tid]);
                    ok = (v0 != 0) && (nb < 2 || v1 != 0) &&
                         (nb < 3 || v2 != 0) && (nb < 4 || v3 != 0);
                } while (!ok);
                excl += (v0 & CNTMASK) + (v1 & CNTMASK) +
                        (v2 & CNTMASK) + (v3 & CNTMASK);
                pt -= nb;
            }
        }
    }

    sm.loc[tid] = loc;
    sm.fix[tid] = (uint32_t)beg + segx + excl - loc;
    __syncthreads();

    // ---- scatter to smem exchange by tile-local rank
#pragma unroll
    for (int j = 0; j < IT; j++) {
        int idx = ibase + j * 32;
        if (idx < tend) {
            uint32_t d = (keys[j] >> shift) & 255u;
            uint32_t r = (rnkp[j >> 1] >> (16 * (j & 1))) & 0xffffu;
            sm.exch[sm.loc[d] + sm.cnt[d][warp] + r] = keys[j];
        }
    }
    __syncthreads();

    // ---- coalesced global pass; inline next-pass histogram (lane-spread)
    float acc = 0.f;
#pragma unroll
    for (int j = 0; j < IT; j++) {
        int p = j * NT + tid;
        if (p < vc) {
            uint32_t k = sm.exch[p];
            uint32_t d = (k >> shift) & 255u;
            uint32_t g = sm.fix[d] + (uint32_t)p;
            if (PASS < 3)
                atomicAdd(&sm.h[lane & 3][(k >> (shift + 8)) & 255u], 1u);
            if (FUSE) acc += fabsf(unflip(k) - init_sorted[g]);
            else      out[g] = k;
        }
    }

    if (PASS < 3) {
        __syncthreads();
        {
            uint32_t v = sm.h[0][tid] + sm.h[1][tid] + sm.h[2][tid] + sm.h[3][tid];
            if (v) atomicAdd(&g_hist[s][PASS + 1][tid], v);
        }
        __syncthreads();   // orders block's writes before release-add
        if (tid == 0) red_release(&g_segdone[PASS][s], 1u);
    }

    if (FUSE) {
#pragma unroll
        for (int o = 16; o; o >>= 1) acc += __shfl_down_sync(FULLMASK, acc, o);
        if (lane == 0) sm.red[warp] = acc;
        __syncthreads();
        if (warp == 0) {
            float v = (lane < NWARP) ? sm.red[lane] : 0.f;
#pragma unroll
            for (int o = 4; o; o >>= 1) v += __shfl_down_sync(FULLMASK, v, o);
            if (lane == 0) g_part[b] = v;
        }
    }
}

// ---------------------------------------------------------------------------
// Persistent driver: pass-major tickets (4 passes, no histogram phase).
// All dependencies are earlier-or-nearby tickets held by resident CTAs
// (lookback: earlier; pass-0 hist aggregation: within +ntiles(s) <= +21,
// far inside the 1184-ticket in-flight window) -> guaranteed progress.
__global__ __launch_bounds__(NT, 8) void k_sort(const float* __restrict__ x,
                                                const float* __restrict__ init) {
    __shared__ SortSmem sm;
    const int ntile = g_toff[NSEG];
    const int ntk   = 4 * ntile;
    for (;;) {
        if (threadIdx.x == 0) sm.tk = (int)atomicAdd(&g_ticket, 1u);
        __syncthreads();
        const int tk = sm.tk;
        if (tk >= ntk) return;
        const int pass = tk / ntile;
        const int b    = tk - pass * ntile;
        switch (pass) {
            case 0:  process_tile<0, false>(b, x, init, sm); break;
            case 1:  process_tile<1, false>(b, x, init, sm); break;
            case 2:  process_tile<2, false>(b, x, init, sm); break;
            default: process_tile<3, true >(b, x, init, sm); break;
        }
        __syncthreads();   // protect sm reuse across tickets
    }
}

// ---------------------------------------------------------------------------
__global__ void k_final(float* __restrict__ outp) {
    __shared__ float sh[256];
    int tid = threadIdx.x;
    float v = 0.f;
    if (tid < NSEG) {
        int len = g_off[tid + 1] - g_off[tid];
        float sum = 0.f;
        for (int t = g_toff[tid]; t < g_toff[tid + 1]; t++) sum += g_part[t];
        v = (len > 0) ? sum / (float)len : 0.f;
    }
    sh[tid] = v;
    __syncthreads();
    for (int o = 128; o; o >>= 1) {
        if (tid < o) sh[tid] += sh[tid + o];
        __syncthreads();
    }
    if (tid == 0) outp[0] = sh[0] * (1e-3f / (float)NSEG);
}

// ---------------------------------------------------------------------------
extern "C" void kernel_launch(void* const* d_in, const int* in_sizes, int n_in,
                              void* d_out, int out_size) {
    const float* x    = (const float*)d_in[0];
    const float* init = (const float*)d_in[1];
    const int*   seg  = (const int*)d_in[2];
    int n = in_sizes[0];

    k_setup<<<1, 256>>>(seg, n);
    k_zero<<<512, 512>>>();
    k_sort<<<GRIDSORT, NT>>>(x, init);
    k_final<<<1, 256>>>((float*)d_out);
}